// round 7
// baseline (speedup 1.0000x reference)
#include <cuda_runtime.h>
#include <cuda_bf16.h>

// x  : (1, 64, 28, 28) fp32 -> (2 groups o, 32 ch j, 28 n, 28 m)
// w1 : (128, 9),  w2 : (32, 7, 9)
// out: (1, 256, 28, 28), channel = o*128 + c, rolled +1 along height.
//
// t4[o,n,m,i]         = sum_{j,k} x[o*32+j, n, m+k-3] * w2[j,k,i]
// out[o,c,(n+1)%28,m] = sum_i w1[c,i] * t4[o,n,m,i]
//
// R6's winning scalar instruction mix, unchanged. Single isolated delta:
// m-axis split in half across blocks -> grid 112 (one wave, 2x SMs).

#define NTHREADS 256

__global__ __launch_bounds__(NTHREADS)
void fused_unfold_einsum_kernel(const float* __restrict__ x,
                                const float* __restrict__ w1,
                                const float* __restrict__ w2,
                                float* __restrict__ out) {
    __shared__ float xs[32][20];        // 14-wide half tile + 3 halo each side
    __shared__ float w2t[9 * 32 * 7];   // transposed: [i][j*7+k]
    __shared__ float w1s[128 * 9];      // [c][i]
    __shared__ float t4s[14 * 9];       // [m_local][i]

    const int tid    = threadIdx.x;
    const int b      = blockIdx.x;      // 0..111
    const int og     = b / 56;          // group 0/1
    const int r      = b - og * 56;
    const int n      = r >> 1;          // input height row
    const int mh     = r & 1;           // m-half
    const int m_base = mh * 14;

    // --- Stage w2 transposed: w2[(j*7+k)*9 + i] -> w2t[i*224 + j*7 + k]
    #pragma unroll
    for (int idx = tid; idx < 9 * 224; idx += NTHREADS) {
        const int i  = idx / 224;
        const int rr = idx - i * 224;   // j*7 + k
        w2t[idx] = w2[rr * 9 + i];
    }
    // --- Stage w1
    #pragma unroll
    for (int idx = tid; idx < 128 * 9; idx += NTHREADS) {
        w1s[idx] = w1[idx];
    }
    // --- Stage x half-row slab with zero halo: cols = m_base-3 .. m_base+16
    #pragma unroll
    for (int idx = tid; idx < 32 * 20; idx += NTHREADS) {
        const int j   = idx / 20;
        const int col = idx - j * 20;
        const int m   = m_base - 3 + col;
        float v = 0.0f;
        if (m >= 0 && m < 28)
            v = x[((og * 32 + j) * 28 + n) * 28 + m];
        xs[j][col] = v;
    }
    __syncthreads();

    // --- t4: thread = (i, m_local), 126 threads. Same scalar mix as R6:
    //     w2t reads ~broadcast across the warp, xs reads consecutive m.
    if (tid < 126) {
        const int i  = tid / 14;
        const int ml = tid - i * 14;
        const float* __restrict__ wrow = &w2t[i * 224];
        float acc_lo = 0.0f;
        float acc_hi = 0.0f;
        #pragma unroll
        for (int j = 0; j < 16; ++j) {
            #pragma unroll
            for (int k = 0; k < 7; ++k) {
                acc_lo = fmaf(xs[j][ml + k], wrow[j * 7 + k], acc_lo);
            }
        }
        #pragma unroll
        for (int j = 16; j < 32; ++j) {
            #pragma unroll
            for (int k = 0; k < 7; ++k) {
                acc_hi = fmaf(xs[j][ml + k], wrow[j * 7 + k], acc_hi);
            }
        }
        t4s[ml * 9 + i] = acc_lo + acc_hi;
    }
    __syncthreads();

    // --- t5 + roll fused into the store index. 1792 outputs, 7 per thread.
    const int nout = (n + 1) % 28;      // jnp.roll(y, +1, axis=2)
    #pragma unroll
    for (int idx = tid; idx < 128 * 14; idx += NTHREADS) {
        const int c  = idx / 14;
        const int ml = idx - c * 14;
        const float* __restrict__ t4m = &t4s[ml * 9];
        const float* __restrict__ w1c = &w1s[c * 9];
        float acc = 0.0f;
        #pragma unroll
        for (int i = 0; i < 9; ++i) {
            acc = fmaf(t4m[i], w1c[i], acc);
        }
        out[((og * 128 + c) * 28 + nout) * 28 + m_base + ml] = acc;
    }
}

extern "C" void kernel_launch(void* const* d_in, const int* in_sizes, int n_in,
                              void* d_out, int out_size) {
    const float* x  = (const float*)d_in[0];
    const float* w1 = (const float*)d_in[1];
    const float* w2 = (const float*)d_in[2];
    float* out = (float*)d_out;
    (void)in_sizes; (void)n_in; (void)out_size;

    fused_unfold_einsum_kernel<<<112, NTHREADS>>>(x, w1, w2, out);
}

// round 8
// speedup vs baseline: 1.0604x; 1.0604x over previous
#include <cuda_runtime.h>
#include <cuda_bf16.h>

// x  : (1, 64, 28, 28) fp32 -> (2 groups o, 32 ch j, 28 n, 28 m)
// w1 : (128, 9),  w2 : (32, 7, 9)
// out: (1, 256, 28, 28), channel = o*128 + c, rolled +1 along height.
//
// t4[o,n,m,i]         = sum_{j,k} x[o*32+j, n, m+k-3] * w2[j,k,i]
// out[o,c,(n+1)%28,m] = sum_i w1[c,i] * t4[o,n,m,i]
//
// R6 scalar mix kept. t4 restructured: thread = (j-half, i, m-pair).
// m-pairing reuses the overlapping x window (8 loads serve 14 FMAs);
// j-split halves per-thread work; smem pair-reduce recombines.

#define NTHREADS 256

__global__ __launch_bounds__(NTHREADS)
void fused_unfold_einsum_kernel(const float* __restrict__ x,
                                const float* __restrict__ w1,
                                const float* __restrict__ w2,
                                float* __restrict__ out) {
    __shared__ float xs[32][34];        // padded width: mm = m+3 in [0,34)
    __shared__ float w2t[9 * 228];      // [i][j*7+k], row stride 228 (bank skew)
    __shared__ float w1s[128 * 9];      // [c][i]
    __shared__ float t4s[28 * 9];       // [m][i]
    __shared__ float t4p[126 * 2];      // j-high partials: [t][m-pair]

    const int tid = threadIdx.x;
    const int b   = blockIdx.x;         // 0..55
    const int og  = b / 28;             // group 0/1
    const int n   = b % 28;             // input height row

    // --- Stage w2 transposed: w2[(j*7+k)*9 + i] -> w2t[i*228 + j*7 + k]
    #pragma unroll
    for (int idx = tid; idx < 9 * 224; idx += NTHREADS) {
        const int i = idx / 224;
        const int r = idx - i * 224;    // j*7 + k
        w2t[i * 228 + r] = w2[r * 9 + i];
    }
    // --- Stage w1
    #pragma unroll
    for (int idx = tid; idx < 128 * 9; idx += NTHREADS) {
        w1s[idx] = w1[idx];
    }
    // --- Stage x row slab with zero halo
    #pragma unroll
    for (int idx = tid; idx < 32 * 34; idx += NTHREADS) {
        const int j  = idx / 34;
        const int mm = idx - j * 34;
        const int m  = mm - 3;
        float v = 0.0f;
        if (m >= 0 && m < 28)
            v = x[((og * 32 + j) * 28 + n) * 28 + m];
        xs[j][mm] = v;
    }
    __syncthreads();

    // --- t4 partials: thread = (half, i, m2). 252 threads, scalar LDS mix.
    float a0 = 0.0f, a1 = 0.0f;
    int t = 0, i = 0, m0 = 0;
    if (tid < 252) {
        const int half = (tid >= 126) ? 1 : 0;
        t  = tid - half * 126;
        i  = t / 14;
        const int m2 = t - i * 14;
        m0 = m2 * 2;
        const int jb = half * 16;
        const float* __restrict__ wrow = &w2t[i * 228 + jb * 7];

        #pragma unroll
        for (int j = 0; j < 16; ++j) {
            const float* __restrict__ xr = &xs[jb + j][m0];
            const float* __restrict__ wr = &wrow[j * 7];
            const float x0 = xr[0], x1 = xr[1], x2 = xr[2], x3 = xr[3];
            const float x4 = xr[4], x5 = xr[5], x6 = xr[6], x7 = xr[7];
            const float w0 = wr[0], w1v = wr[1], w2v = wr[2], w3 = wr[3];
            const float w4 = wr[4], w5 = wr[5], w6 = wr[6];
            a0 = fmaf(x0, w0,  a0);  a1 = fmaf(x1, w0,  a1);
            a0 = fmaf(x1, w1v, a0);  a1 = fmaf(x2, w1v, a1);
            a0 = fmaf(x2, w2v, a0);  a1 = fmaf(x3, w2v, a1);
            a0 = fmaf(x3, w3,  a0);  a1 = fmaf(x4, w3,  a1);
            a0 = fmaf(x4, w4,  a0);  a1 = fmaf(x5, w4,  a1);
            a0 = fmaf(x5, w5,  a0);  a1 = fmaf(x6, w5,  a1);
            a0 = fmaf(x6, w6,  a0);  a1 = fmaf(x7, w6,  a1);
        }
        if (half) {
            t4p[t * 2 + 0] = a0;
            t4p[t * 2 + 1] = a1;
        }
    }
    __syncthreads();

    // --- Recombine j-halves (threads 0..125 hold the j<16 partials).
    if (tid < 126) {
        t4s[(m0 + 0) * 9 + i] = a0 + t4p[t * 2 + 0];
        t4s[(m0 + 1) * 9 + i] = a1 + t4p[t * 2 + 1];
    }
    __syncthreads();

    // --- t5 + roll fused into the store index (R6 verbatim).
    const int nout = (n + 1) % 28;      // jnp.roll(y, +1, axis=2)
    #pragma unroll
    for (int idx = tid; idx < 128 * 28; idx += NTHREADS) {
        const int c = idx / 28;
        const int m = idx - c * 28;
        const float* __restrict__ t4m = &t4s[m * 9];
        const float* __restrict__ w1c = &w1s[c * 9];
        float acc = 0.0f;
        #pragma unroll
        for (int ii = 0; ii < 9; ++ii) {
            acc = fmaf(t4m[ii], w1c[ii], acc);
        }
        out[((og * 128 + c) * 28 + nout) * 28 + m] = acc;
    }
}

extern "C" void kernel_launch(void* const* d_in, const int* in_sizes, int n_in,
                              void* d_out, int out_size) {
    const float* x  = (const float*)d_in[0];
    const float* w1 = (const float*)d_in[1];
    const float* w2 = (const float*)d_in[2];
    float* out = (float*)d_out;
    (void)in_sizes; (void)n_in; (void)out_size;

    fused_unfold_einsum_kernel<<<56, NTHREADS>>>(x, w1, w2, out);
}

// round 9
// speedup vs baseline: 1.0766x; 1.0153x over previous
#include <cuda_runtime.h>
#include <cuda_bf16.h>

// x  : (1, 64, 28, 28) fp32 -> (2 groups o, 32 ch j, 28 n, 28 m)
// w1 : (128, 9),  w2 : (32, 7, 9)
// out: (1, 256, 28, 28), channel = o*128 + c, rolled +1 along height.
//
// t4[o,n,m,i]         = sum_{j,k} x[o*32+j, n, m+k-3] * w2[j,k,i]
// out[o,c,(n+1)%28,m] = sum_i w1[c,i] * t4[o,n,m,i]
//
// R8 t4 kept verbatim. Deltas: w1 prefetched to registers at entry (latency
// hidden under staging+t4), phase 2 made c-major with reg-resident w1 and
// STG.128 output stores.

#define NTHREADS 256

__global__ __launch_bounds__(NTHREADS)
void fused_unfold_einsum_kernel(const float* __restrict__ x,
                                const float* __restrict__ w1,
                                const float* __restrict__ w2,
                                float* __restrict__ out) {
    __shared__ float xs[32][34];        // padded width: mm = m+3 in [0,34)
    __shared__ float w2t[9 * 228];      // [i][j*7+k], row stride 228 (bank skew)
    __shared__ float t4s[28 * 9];       // [m][i]
    __shared__ float t4p[126 * 2];      // j-high partials: [t][m-pair]

    const int tid = threadIdx.x;
    const int b   = blockIdx.x;         // 0..55
    const int og  = b / 28;             // group 0/1
    const int n   = b % 28;             // input height row

    // --- Prefetch this thread's w1 row into registers (consumed in phase 2;
    //     ~600cyc LDG latency hidden behind staging + t4 + 2 barriers).
    const int c    = tid & 127;
    const int mseg = tid >> 7;          // 0: m in [0,16), 1: m in [16,28)
    float w1r[9];
    #pragma unroll
    for (int ii = 0; ii < 9; ++ii)
        w1r[ii] = __ldg(&w1[c * 9 + ii]);

    // --- Stage w2 transposed: w2[(j*7+k)*9 + i] -> w2t[i*228 + j*7 + k]
    #pragma unroll
    for (int idx = tid; idx < 9 * 224; idx += NTHREADS) {
        const int i = idx / 224;
        const int r = idx - i * 224;    // j*7 + k
        w2t[i * 228 + r] = w2[r * 9 + i];
    }
    // --- Stage x row slab with zero halo
    #pragma unroll
    for (int idx = tid; idx < 32 * 34; idx += NTHREADS) {
        const int j  = idx / 34;
        const int mm = idx - j * 34;
        const int m  = mm - 3;
        float v = 0.0f;
        if (m >= 0 && m < 28)
            v = x[((og * 32 + j) * 28 + n) * 28 + m];
        xs[j][mm] = v;
    }
    __syncthreads();

    // --- t4 partials (R8 verbatim): thread = (j-half, i, m-pair). 252 threads.
    float a0 = 0.0f, a1 = 0.0f;
    int t = 0, i = 0, m0 = 0;
    if (tid < 252) {
        const int half = (tid >= 126) ? 1 : 0;
        t  = tid - half * 126;
        i  = t / 14;
        const int m2 = t - i * 14;
        m0 = m2 * 2;
        const int jb = half * 16;
        const float* __restrict__ wrow = &w2t[i * 228 + jb * 7];

        #pragma unroll
        for (int j = 0; j < 16; ++j) {
            const float* __restrict__ xr = &xs[jb + j][m0];
            const float* __restrict__ wr = &wrow[j * 7];
            const float x0 = xr[0], x1 = xr[1], x2 = xr[2], x3 = xr[3];
            const float x4 = xr[4], x5 = xr[5], x6 = xr[6], x7 = xr[7];
            const float w0 = wr[0], w1v = wr[1], w2v = wr[2], w3 = wr[3];
            const float w4 = wr[4], w5 = wr[5], w6 = wr[6];
            a0 = fmaf(x0, w0,  a0);  a1 = fmaf(x1, w0,  a1);
            a0 = fmaf(x1, w1v, a0);  a1 = fmaf(x2, w1v, a1);
            a0 = fmaf(x2, w2v, a0);  a1 = fmaf(x3, w2v, a1);
            a0 = fmaf(x3, w3,  a0);  a1 = fmaf(x4, w3,  a1);
            a0 = fmaf(x4, w4,  a0);  a1 = fmaf(x5, w4,  a1);
            a0 = fmaf(x5, w5,  a0);  a1 = fmaf(x6, w5,  a1);
            a0 = fmaf(x6, w6,  a0);  a1 = fmaf(x7, w6,  a1);
        }
        if (half) {
            t4p[t * 2 + 0] = a0;
            t4p[t * 2 + 1] = a1;
        }
    }
    __syncthreads();

    // --- Recombine j-halves (threads 0..125 hold the j<16 partials).
    if (tid < 126) {
        t4s[(m0 + 0) * 9 + i] = a0 + t4p[t * 2 + 0];
        t4s[(m0 + 1) * 9 + i] = a1 + t4p[t * 2 + 1];
    }
    __syncthreads();

    // --- Phase 2, c-major: one c per thread, w1 in registers, t4s reads are
    //     warp-broadcast, 4 m's fused per aligned STG.128.
    const int nout = (n + 1) % 28;          // jnp.roll(y, +1, axis=2)
    const int mbase = mseg * 16;            // 0 or 16
    const int ngrp  = mseg ? 3 : 4;         // 12 or 16 m's
    float* __restrict__ orow = &out[((og * 128 + c) * 28 + nout) * 28];

    #pragma unroll
    for (int gq = 0; gq < 4; ++gq) {
        if (gq < ngrp) {                    // warp-uniform predicate
            float o4[4];
            #pragma unroll
            for (int qq = 0; qq < 4; ++qq) {
                const int m = mbase + gq * 4 + qq;
                const float* __restrict__ t4m = &t4s[m * 9];
                float acc = t4m[0] * w1r[0];
                #pragma unroll
                for (int ii = 1; ii < 9; ++ii)
                    acc = fmaf(t4m[ii], w1r[ii], acc);
                o4[qq] = acc;
            }
            *reinterpret_cast<float4*>(&orow[mbase + gq * 4]) =
                make_float4(o4[0], o4[1], o4[2], o4[3]);
        }
    }
}

extern "C" void kernel_launch(void* const* d_in, const int* in_sizes, int n_in,
                              void* d_out, int out_size) {
    const float* x  = (const float*)d_in[0];
    const float* w1 = (const float*)d_in[1];
    const float* w2 = (const float*)d_in[2];
    float* out = (float*)d_out;
    (void)in_sizes; (void)n_in; (void)out_size;

    fused_unfold_einsum_kernel<<<56, NTHREADS>>>(x, w1, w2, out);
}

// round 10
// speedup vs baseline: 1.0977x; 1.0195x over previous
#include <cuda_runtime.h>
#include <cuda_bf16.h>

// x  : (1, 64, 28, 28) fp32 -> (2 groups o, 32 ch j, 28 n, 28 m)
// w1 : (128, 9),  w2 : (32, 7, 9)
// out: (1, 256, 28, 28), channel = o*128 + c, rolled +1 along height.
//
// t4[o,n,m,i]         = sum_{j,k} x[o*32+j, n, m+k-3] * w2[j,k,i]
// out[o,c,(n+1)%28,m] = sum_i w1[c,i] * t4[o,n,m,i]
//
// R9 structure; loads vectorized where provably parallel:
//   t4 x: LDS.64 (m0 even), t4 w: 2x LDS.128 ([i][j*8+k] pad layout),
//   phase2 t4s: 3x LDS.128 (stride 12). Same FMA order as R8/R9.

#define NTHREADS 256

__global__ __launch_bounds__(NTHREADS)
void fused_unfold_einsum_kernel(const float* __restrict__ x,
                                const float* __restrict__ w1,
                                const float* __restrict__ w2,
                                float* __restrict__ out) {
    __shared__ __align__(16) float xs[32][34];   // mm = m+3 in [0,34); stride even
    __shared__ __align__(16) float w2t[9 * 264]; // [i][j*8 + k], k padded to 8
    __shared__ __align__(16) float t4s[28 * 12]; // [m][i], stride 12 for LDS.128
    __shared__ __align__(16) float t4p[126 * 2]; // j-high partials

    const int tid = threadIdx.x;
    const int b   = blockIdx.x;         // 0..55
    const int og  = b / 28;
    const int n   = b % 28;

    // --- Prefetch this thread's w1 row to registers (used in phase 2).
    const int c    = tid & 127;
    const int mseg = tid >> 7;
    float w1r[9];
    #pragma unroll
    for (int ii = 0; ii < 9; ++ii)
        w1r[ii] = __ldg(&w1[c * 9 + ii]);

    // --- Stage w2: coalesced linear read, scatter to [i][j*8+k] (k-pad unused).
    #pragma unroll
    for (int idx = tid; idx < 2016; idx += NTHREADS) {   // 2016 = 32*7*9
        const int r = idx / 9;          // j*7 + k
        const int i = idx - r * 9;
        const int j = r / 7;
        const int k = r - j * 7;
        w2t[i * 264 + j * 8 + k] = w2[idx];
    }
    // --- Stage x row slab with zero halo (R9 verbatim).
    #pragma unroll
    for (int idx = tid; idx < 32 * 34; idx += NTHREADS) {
        const int j  = idx / 34;
        const int mm = idx - j * 34;
        const int m  = mm - 3;
        float v = 0.0f;
        if (m >= 0 && m < 28)
            v = x[((og * 32 + j) * 28 + n) * 28 + m];
        xs[j][mm] = v;
    }
    __syncthreads();

    // --- t4 partials: thread = (j-half, i, m-pair). 252 threads.
    float a0 = 0.0f, a1 = 0.0f;
    int t = 0, i = 0, m0 = 0;
    if (tid < 252) {
        const int half = (tid >= 126) ? 1 : 0;
        t  = tid - half * 126;
        i  = t / 14;
        const int m2 = t - i * 14;
        m0 = m2 * 2;
        const int jb = half * 16;
        const float* __restrict__ wrow = &w2t[i * 264 + jb * 8];

        #pragma unroll
        for (int j = 0; j < 16; ++j) {
            const float2* __restrict__ xr =
                reinterpret_cast<const float2*>(&xs[jb + j][m0]);   // 8B aligned
            const float4* __restrict__ wv =
                reinterpret_cast<const float4*>(&wrow[j * 8]);      // 16B aligned
            const float2 p0 = xr[0], p1 = xr[1], p2 = xr[2], p3 = xr[3];
            const float4 wa = wv[0], wb = wv[1];    // wb.w = pad, unused
            const float x0 = p0.x, x1 = p0.y, x2 = p1.x, x3 = p1.y;
            const float x4 = p2.x, x5 = p2.y, x6 = p3.x, x7 = p3.y;
            a0 = fmaf(x0, wa.x, a0);  a1 = fmaf(x1, wa.x, a1);
            a0 = fmaf(x1, wa.y, a0);  a1 = fmaf(x2, wa.y, a1);
            a0 = fmaf(x2, wa.z, a0);  a1 = fmaf(x3, wa.z, a1);
            a0 = fmaf(x3, wa.w, a0);  a1 = fmaf(x4, wa.w, a1);
            a0 = fmaf(x4, wb.x, a0);  a1 = fmaf(x5, wb.x, a1);
            a0 = fmaf(x5, wb.y, a0);  a1 = fmaf(x6, wb.y, a1);
            a0 = fmaf(x6, wb.z, a0);  a1 = fmaf(x7, wb.z, a1);
        }
        if (half) {
            t4p[t * 2 + 0] = a0;
            t4p[t * 2 + 1] = a1;
        }
    }
    __syncthreads();

    // --- Recombine j-halves into stride-12 t4s.
    if (tid < 126) {
        t4s[(m0 + 0) * 12 + i] = a0 + t4p[t * 2 + 0];
        t4s[(m0 + 1) * 12 + i] = a1 + t4p[t * 2 + 1];
    }
    __syncthreads();

    // --- Phase 2, c-major: w1 in registers, t4s via 3x broadcast LDS.128,
    //     4 m's per aligned STG.128.
    const int nout  = (n + 1) % 28;     // jnp.roll(y, +1, axis=2)
    const int mbase = mseg * 16;        // 0 or 16
    const int ngrp  = mseg ? 3 : 4;     // 12 or 16 m's
    float* __restrict__ orow = &out[((og * 128 + c) * 28 + nout) * 28];

    #pragma unroll
    for (int gq = 0; gq < 4; ++gq) {
        if (gq < ngrp) {                // warp-uniform predicate
            float o4[4];
            #pragma unroll
            for (int qq = 0; qq < 4; ++qq) {
                const int m = mbase + gq * 4 + qq;
                const float4* __restrict__ tv =
                    reinterpret_cast<const float4*>(&t4s[m * 12]);
                const float4 v0 = tv[0], v1 = tv[1], v2 = tv[2]; // v2.y/z/w pad
                float acc = v0.x * w1r[0];
                acc = fmaf(v0.y, w1r[1], acc);
                acc = fmaf(v0.z, w1r[2], acc);
                acc = fmaf(v0.w, w1r[3], acc);
                acc = fmaf(v1.x, w1r[4], acc);
                acc = fmaf(v1.y, w1r[5], acc);
                acc = fmaf(v1.z, w1r[6], acc);
                acc = fmaf(v1.w, w1r[7], acc);
                acc = fmaf(v2.x, w1r[8], acc);
                o4[qq] = acc;
            }
            *reinterpret_cast<float4*>(&orow[mbase + gq * 4]) =
                make_float4(o4[0], o4[1], o4[2], o4[3]);
        }
    }
}

extern "C" void kernel_launch(void* const* d_in, const int* in_sizes, int n_in,
                              void* d_out, int out_size) {
    const float* x  = (const float*)d_in[0];
    const float* w1 = (const float*)d_in[1];
    const float* w2 = (const float*)d_in[2];
    float* out = (float*)d_out;
    (void)in_sizes; (void)n_in; (void)out_size;

    fused_unfold_einsum_kernel<<<56, NTHREADS>>>(x, w1, w2, out);
}

// round 11
// speedup vs baseline: 1.1107x; 1.0119x over previous
#include <cuda_runtime.h>
#include <cuda_bf16.h>

// x  : (1, 64, 28, 28) fp32 -> (2 groups o, 32 ch j, 28 n, 28 m)
// w1 : (128, 9),  w2 : (32, 7, 9)
// out: (1, 256, 28, 28), channel = o*128 + c, rolled +1 along height.
//
// t4[o,n,m,i]         = sum_{j,k} x[o*32+j, n, m+k-3] * w2[j,k,i]
// out[o,c,(n+1)%28,m] = sum_i w1[c,i] * t4[o,n,m,i]
//
// R10 phase2/staging kept. t4 rebuilt around packed fma.rn.f32x2:
// thread = (j-quarter, i, m-quad). Even-k -> acc pairs (m0,m1),(m2,m3);
// odd-k -> acc pair (m1,m2) + 2 scalar FMAs. All packed operands are
// naturally-aligned LDS.64 words (weights pre-duplicated in smem).

#define NTHREADS 256

union UF2 {
    unsigned long long u;
    float2 f;
};

#define FFMA2(acc, a, b) \
    asm("fma.rn.f32x2 %0, %1, %2, %0;" : "+l"(acc) : "l"(a), "l"(b))

__global__ __launch_bounds__(NTHREADS)
void fused_unfold_einsum_kernel(const float* __restrict__ x,
                                const float* __restrict__ w1,
                                const float* __restrict__ w2,
                                float* __restrict__ out) {
    __shared__ __align__(16) float xs[32][34];    // mm = m+3 in [0,34)
    __shared__ __align__(16) float w2d[9 * 516];  // [i][j*16 + k*2] = (w,w) pairs
    __shared__ __align__(16) float t4s[28 * 12];  // [m][i], stride 12
    __shared__ __align__(16) float4 t4p[3 * 63];  // quarter partials [q-1][t]

    const int tid = threadIdx.x;
    const int b   = blockIdx.x;         // 0..55
    const int og  = b / 28;
    const int n   = b % 28;

    // --- Prefetch this thread's w1 row to registers (phase 2).
    const int c    = tid & 127;
    const int mseg = tid >> 7;
    float w1r[9];
    #pragma unroll
    for (int ii = 0; ii < 9; ++ii)
        w1r[ii] = __ldg(&w1[c * 9 + ii]);

    // --- Stage w2 as duplicated (w,w) pairs: w2d[i*516 + j*16 + k*2 (+1)]
    #pragma unroll
    for (int idx = tid; idx < 2016; idx += NTHREADS) {   // 32*7*9
        const int r = idx / 9;          // j*7 + k
        const int i = idx - r * 9;
        const int j = r / 7;
        const int k = r - j * 7;
        const float v = w2[idx];
        const int d = i * 516 + j * 16 + k * 2;
        w2d[d]     = v;
        w2d[d + 1] = v;
    }
    // --- Stage x row slab with zero halo.
    #pragma unroll
    for (int idx = tid; idx < 32 * 34; idx += NTHREADS) {
        const int j  = idx / 34;
        const int mm = idx - j * 34;
        const int m  = mm - 3;
        float v = 0.0f;
        if (m >= 0 && m < 28)
            v = x[((og * 32 + j) * 28 + n) * 28 + m];
        xs[j][mm] = v;
    }
    __syncthreads();

    // --- t4 partials: thread = (j-quarter q, i, m-quad). 252 threads.
    float r0 = 0.f, r1 = 0.f, r2 = 0.f, r3 = 0.f;
    int t = 0, i = 0, m0 = 0;
    if (tid < 252) {
        const int q  = tid / 63;
        t  = tid - q * 63;
        i  = t / 7;
        const int mq = t - i * 7;
        m0 = mq * 4;
        const int jb = q * 8;

        UF2 A, B, C;                // A=(m0,m1) even-k, B=(m2,m3) even-k, C=(m1,m2) odd-k
        A.u = 0; B.u = 0; C.u = 0;
        float s0 = 0.f, s3 = 0.f;   // m0 / m3 odd-k scalar tails

        #pragma unroll
        for (int j = 0; j < 8; ++j) {
            const int row = jb + j;
            const unsigned long long* __restrict__ xp =
                reinterpret_cast<const unsigned long long*>(&xs[row][m0]); // 8B aligned
            const unsigned long long* __restrict__ wp =
                reinterpret_cast<const unsigned long long*>(&w2d[i * 516 + row * 16]);
            UF2 P0, P1, P2, P3, P4;         // x[m0+0..9] as aligned pairs
            P0.u = xp[0]; P1.u = xp[1]; P2.u = xp[2]; P3.u = xp[3]; P4.u = xp[4];
            const unsigned long long W0 = wp[0], W1 = wp[1], W2 = wp[2],
                                     W3 = wp[3], W4 = wp[4], W5 = wp[5], W6 = wp[6];
            UF2 W1s, W3s, W5s;              // scalar views of odd weights
            W1s.u = W1; W3s.u = W3; W5s.u = W5;

            // even k: aligned pairs into A, B
            FFMA2(A.u, P0.u, W0);  FFMA2(B.u, P1.u, W0);   // k=0
            FFMA2(A.u, P1.u, W2);  FFMA2(B.u, P2.u, W2);   // k=2
            FFMA2(A.u, P2.u, W4);  FFMA2(B.u, P3.u, W4);   // k=4
            FFMA2(A.u, P3.u, W6);  FFMA2(B.u, P4.u, W6);   // k=6
            // odd k: (m1,m2) pairs are aligned too
            FFMA2(C.u, P1.u, W1);                          // k=1
            FFMA2(C.u, P2.u, W3);                          // k=3
            FFMA2(C.u, P3.u, W5);                          // k=5
            // odd-k scalar tails for m0 and m3 (free component reads)
            s0 = fmaf(P0.f.y, W1s.f.x, s0);   // x[m0+1]*w1
            s0 = fmaf(P1.f.y, W3s.f.x, s0);   // x[m0+3]*w3
            s0 = fmaf(P2.f.y, W5s.f.x, s0);   // x[m0+5]*w5
            s3 = fmaf(P2.f.x, W1s.f.x, s3);   // x[m0+4]*w1
            s3 = fmaf(P3.f.x, W3s.f.x, s3);   // x[m0+6]*w3
            s3 = fmaf(P4.f.x, W5s.f.x, s3);   // x[m0+8]*w5
        }
        r0 = A.f.x + s0;
        r1 = A.f.y + C.f.x;
        r2 = B.f.x + C.f.y;
        r3 = B.f.y + s3;
        if (q > 0)
            t4p[(q - 1) * 63 + t] = make_float4(r0, r1, r2, r3);
    }
    __syncthreads();

    // --- Recombine the 4 j-quarters (threads 0..62 hold quarter 0).
    if (tid < 63) {
        const float4 u1 = t4p[t];
        const float4 u2 = t4p[63 + t];
        const float4 u3 = t4p[126 + t];
        t4s[(m0 + 0) * 12 + i] = r0 + u1.x + u2.x + u3.x;
        t4s[(m0 + 1) * 12 + i] = r1 + u1.y + u2.y + u3.y;
        t4s[(m0 + 2) * 12 + i] = r2 + u1.z + u2.z + u3.z;
        t4s[(m0 + 3) * 12 + i] = r3 + u1.w + u2.w + u3.w;
    }
    __syncthreads();

    // --- Phase 2 (R10 verbatim): c-major, w1 in regs, 3x LDS.128, STG.128.
    const int nout  = (n + 1) % 28;     // jnp.roll(y, +1, axis=2)
    const int mbase = mseg * 16;
    const int ngrp  = mseg ? 3 : 4;
    float* __restrict__ orow = &out[((og * 128 + c) * 28 + nout) * 28];

    #pragma unroll
    for (int gq = 0; gq < 4; ++gq) {
        if (gq < ngrp) {                // warp-uniform predicate
            float o4[4];
            #pragma unroll
            for (int qq = 0; qq < 4; ++qq) {
                const int m = mbase + gq * 4 + qq;
                const float4* __restrict__ tv =
                    reinterpret_cast<const float4*>(&t4s[m * 12]);
                const float4 v0 = tv[0], v1 = tv[1], v2 = tv[2];
                float acc = v0.x * w1r[0];
                acc = fmaf(v0.y, w1r[1], acc);
                acc = fmaf(v0.z, w1r[2], acc);
                acc = fmaf(v0.w, w1r[3], acc);
                acc = fmaf(v1.x, w1r[4], acc);
                acc = fmaf(v1.y, w1r[5], acc);
                acc = fmaf(v1.z, w1r[6], acc);
                acc = fmaf(v1.w, w1r[7], acc);
                acc = fmaf(v2.x, w1r[8], acc);
                o4[qq] = acc;
            }
            *reinterpret_cast<float4*>(&orow[mbase + gq * 4]) =
                make_float4(o4[0], o4[1], o4[2], o4[3]);
        }
    }
}

extern "C" void kernel_launch(void* const* d_in, const int* in_sizes, int n_in,
                              void* d_out, int out_size) {
    const float* x  = (const float*)d_in[0];
    const float* w1 = (const float*)d_in[1];
    const float* w2 = (const float*)d_in[2];
    float* out = (float*)d_out;
    (void)in_sizes; (void)n_in; (void)out_size;

    fused_unfold_einsum_kernel<<<56, NTHREADS>>>(x, w1, w2, out);
}